// round 8
// baseline (speedup 1.0000x reference)
#include <cuda_runtime.h>

typedef unsigned long long u64;

#define BATCH 64
#define TLEN  2048
#define TM1   2047
#define CIN   8
#define MD    16
#define NOUT  10

#define CHUNK  64
#define NCHUNK 32            // 32*64 = 2048 >= 2047 (tail -> identity)
#define NGRP   8             // 16-thread groups per block
#define SPG    8             // steps per group (processed as 4 pairs)
#define STR    20            // padded row stride (floats)
#define SLOT   (MD*STR)      // 320 floats per matrix slot
#define GSTR   (3*SLOT + 4)  // per-group: sA + sB + sZ + pad

// chunk partial products: [B][NCHUNK][16][16]
__device__ float g_partial[BATCH * NCHUNK * MD * MD];

// ---- packed f32x2 helpers ----
__device__ __forceinline__ float2 unpk(u64 v) {
  float2 r; asm("mov.b64 {%0,%1}, %2;" : "=f"(r.x), "=f"(r.y) : "l"(v)); return r;
}
__device__ __forceinline__ u64 pk2(float x, float y) {
  u64 r; asm("mov.b64 %0, {%1,%2};" : "=l"(r) : "f"(x), "f"(y)); return r;
}
__device__ __forceinline__ u64 bc2(float x) {
  u64 r; asm("mov.b64 %0, {%1,%1};" : "=l"(r) : "f"(x)); return r;
}
__device__ __forceinline__ void fma2(u64& d, u64 a, u64 b) {
  asm("fma.rn.f32x2 %0, %1, %2, %0;" : "+l"(d) : "l"(a), "l"(b));
}
__device__ __forceinline__ u64 fma2v(u64 a, u64 b, u64 c) {
  u64 d; asm("fma.rn.f32x2 %0, %1, %2, %3;" : "=l"(d) : "l"(a), "l"(b), "l"(c)); return d;
}
__device__ __forceinline__ u64 mul2(u64 a, u64 b) {
  u64 d; asm("mul.rn.f32x2 %0, %1, %2;" : "=l"(d) : "l"(a), "l"(b)); return d;
}

// acc += av * Brow (16 floats in smem, 16B-aligned)
__device__ __forceinline__ void row_fma(u64* acc, u64 av, const float* brow) {
  const ulonglong2* bp = reinterpret_cast<const ulonglong2*>(brow);
  ulonglong2 b0 = bp[0], b1 = bp[1], b2 = bp[2], b3 = bp[3];
  fma2(acc[0], av, b0.x); fma2(acc[1], av, b0.y);
  fma2(acc[2], av, b1.x); fma2(acc[3], av, b1.y);
  fma2(acc[4], av, b2.x); fma2(acc[5], av, b2.y);
  fma2(acc[6], av, b3.x); fma2(acc[7], av, b3.y);
}

// single-stream: acc(row) += a(row regs) @ Bm
__device__ __forceinline__ void mm_row2(const float* __restrict__ Bm,
                                        const u64* __restrict__ a,
                                        u64* __restrict__ acc) {
#pragma unroll
  for (int kp = 0; kp < 8; kp++) {
    float2 ak = unpk(a[kp]);
    row_fma(acc, bc2(ak.x), Bm + (2 * kp) * STR);
    row_fma(acc, bc2(ak.y), Bm + (2 * kp + 1) * STR);
  }
}

// fused pair: two independent matmuls interleaved (2x ILP, shared loop)
__device__ __forceinline__ void mm_pair(const float* __restrict__ Ba,
                                        const float* __restrict__ Bb,
                                        const u64* __restrict__ a,
                                        const u64* __restrict__ b,
                                        u64* __restrict__ aa,
                                        u64* __restrict__ ab) {
#pragma unroll
  for (int kp = 0; kp < 8; kp++) {
    float2 xa = unpk(a[kp]);
    float2 xb = unpk(b[kp]);
    row_fma(aa, bc2(xa.x), Ba + (2 * kp) * STR);
    row_fma(ab, bc2(xb.x), Bb + (2 * kp) * STR);
    row_fma(aa, bc2(xa.y), Ba + (2 * kp + 1) * STR);
    row_fma(ab, bc2(xb.y), Bb + (2 * kp + 1) * STR);
  }
}

__device__ __forceinline__ void store_row2(float* dst, const u64* v) {
  ulonglong2* dp = reinterpret_cast<ulonglong2*>(dst);
  dp[0] = make_ulonglong2(v[0], v[1]);
  dp[1] = make_ulonglong2(v[2], v[3]);
  dp[2] = make_ulonglong2(v[4], v[5]);
  dp[3] = make_ulonglong2(v[6], v[7]);
}
__device__ __forceinline__ void load_row2(const float* src, u64* v) {
  const ulonglong2* sp = reinterpret_cast<const ulonglong2*>(src);
  ulonglong2 a = sp[0], b = sp[1], c = sp[2], d = sp[3];
  v[0] = a.x; v[1] = a.y; v[2] = b.x; v[3] = b.y;
  v[4] = c.x; v[5] = c.y; v[6] = d.x; v[7] = d.y;
}

// pad kernel: shifts ncu "-s 5 -c 1" onto dev_chunks (period-4 launches)
__global__ void nopk() {}

// ---------------------------------------------------------------------------
// Kernel 1: per (batch, chunk of 64 steps). 16-thread groups, 1 row/thread.
// Steps processed in PAIRS: two independent expm streams (R6's exact
// commuting-Horner Taylor-6 at theta<=0.25 + warp-uniform squarings) run
// interleaved through fused matmuls, then pair-product + fold.
// ---------------------------------------------------------------------------
__global__ void __launch_bounds__(128) dev_chunks(const float* __restrict__ X,
                                                  const float* __restrict__ A) {
  __shared__ __align__(16) float Gs[CIN * SLOT];
  __shared__ __align__(16) float slots[NGRP * GSTR];
  __shared__ float dxs[CHUNK * CIN];

  const int tid   = threadIdx.x;
  const int chunk = blockIdx.x;
  const int b     = blockIdx.y;
  const int base  = chunk * CHUNK;

  for (int idx = tid; idx < CIN * MD * MD; idx += 128) {
    int c = idx >> 8;
    int i = (idx >> 4) & 15;
    int j = idx & 15;
    Gs[c * SLOT + i * STR + j] =
        A[(i * MD + j) * CIN + c] - A[(j * MD + i) * CIN + c];
  }
  for (int idx = tid; idx < CHUNK * CIN; idx += 128) {
    int k = idx >> 3;
    int c = idx & 7;
    int t = base + k;
    float v = 0.f;
    if (t < TM1)
      v = X[(b * TLEN + t + 1) * CIN + c] - X[(b * TLEN + t) * CIN + c];
    dxs[idx] = v;
  }
  __syncthreads();

  const int grp = tid >> 4;
  const int li  = tid & 15;
  float* sA = slots + grp * GSTR;   // stream-a S / scratch
  float* sB = sA + SLOT;            // stream-b S / scratch
  float* sZ = sB + SLOT;            // running product Z

  u64 idp[8];
#pragma unroll
  for (int p = 0; p < 8; p++)
    idp[p] = pk2((li == 2 * p) ? 1.f : 0.f, (li == 2 * p + 1) ? 1.f : 0.f);

  for (int kl = 0; kl < SPG; kl += 2) {
    const int kk = grp * SPG + kl;

    // ---- build S for both steps of the pair ----
    u64 Sa[8], Sb[8];
#pragma unroll
    for (int p = 0; p < 8; p++) { Sa[p] = 0ull; Sb[p] = 0ull; }
#pragma unroll
    for (int c = 0; c < CIN; c++) {
      const float* grow = Gs + c * SLOT + li * STR;
      u64 da = bc2(dxs[kk * CIN + c]);
      u64 db = bc2(dxs[(kk + 1) * CIN + c]);
      const ulonglong2* bp = reinterpret_cast<const ulonglong2*>(grow);
      ulonglong2 g0 = bp[0], g1 = bp[1], g2 = bp[2], g3 = bp[3];
      fma2(Sa[0], da, g0.x); fma2(Sb[0], db, g0.x);
      fma2(Sa[1], da, g0.y); fma2(Sb[1], db, g0.y);
      fma2(Sa[2], da, g1.x); fma2(Sb[2], db, g1.x);
      fma2(Sa[3], da, g1.y); fma2(Sb[3], db, g1.y);
      fma2(Sa[4], da, g2.x); fma2(Sb[4], db, g2.x);
      fma2(Sa[5], da, g2.y); fma2(Sb[5], db, g2.y);
      fma2(Sa[6], da, g3.x); fma2(Sb[6], db, g3.x);
      fma2(Sa[7], da, g3.y); fma2(Sb[7], db, g3.y);
    }

    // ---- norms (per stream): min(inf, Frobenius/sqrt2); warp-uniform s ----
    float ra = 0.f, fa = 0.f, rb = 0.f, fb = 0.f;
#pragma unroll
    for (int p = 0; p < 8; p++) {
      float2 ta = unpk(Sa[p]), tb = unpk(Sb[p]);
      ra += fabsf(ta.x) + fabsf(ta.y);
      rb += fabsf(tb.x) + fabsf(tb.y);
      fa = fmaf(ta.x, ta.x, fa); fa = fmaf(ta.y, ta.y, fa);
      fb = fmaf(tb.x, tb.x, fb); fb = fmaf(tb.y, tb.y, fb);
    }
#pragma unroll
    for (int off = 1; off < 16; off <<= 1) {
      ra = fmaxf(ra, __shfl_xor_sync(0xffffffffu, ra, off));
      rb = fmaxf(rb, __shfl_xor_sync(0xffffffffu, rb, off));
      fa += __shfl_xor_sync(0xffffffffu, fa, off);
      fb += __shfl_xor_sync(0xffffffffu, fb, off);
    }
    float nrm = fmaxf(fminf(ra, sqrtf(0.5f * fa)),
                      fminf(rb, sqrtf(0.5f * fb)));
    nrm = fmaxf(nrm, __shfl_xor_sync(0xffffffffu, nrm, 16));  // warp-uniform
    int s = 0;
    if (nrm > 0.f) {
      int e;
      frexpf(nrm, &e);   // nrm = f * 2^e, f in [0.5,1)
      s = e + 2;         // ||S/2^s|| <= 0.25
      if (s < 0) s = 0;
      if (s > 40) s = 40;
    }
    const u64 sc2 = bc2(__int_as_float((127 - s) << 23));  // exact 2^-s
#pragma unroll
    for (int p = 0; p < 8; p++) { Sa[p] = mul2(Sa[p], sc2); Sb[p] = mul2(Sb[p], sc2); }

    // store both S matrices (prior pair's trailing sync covers old readers)
    store_row2(sA + li * STR, Sa);
    store_row2(sB + li * STR, Sb);
    // init Horner from registers before S regs die
    u64 ca[8], cb[8];
    {
      const u64 c6 = bc2(1.f / 6.f);
#pragma unroll
      for (int p = 0; p < 8; p++) {
        ca[p] = fma2v(Sa[p], c6, idp[p]);
        cb[p] = fma2v(Sb[p], c6, idp[p]);
      }
    }
    __syncwarp();

    // ---- commuting-Horner Taylor-6, both streams fused ----
#pragma unroll
    for (int k = 5; k >= 1; k--) {
      u64 aa[8], ab[8];
#pragma unroll
      for (int p = 0; p < 8; p++) { aa[p] = 0ull; ab[p] = 0ull; }
      mm_pair(sA, sB, ca, cb, aa, ab);
      const u64 inv = bc2(1.f / (float)k);
#pragma unroll
      for (int p = 0; p < 8; p++) {
        ca[p] = fma2v(aa[p], inv, idp[p]);
        cb[p] = fma2v(ab[p], inv, idp[p]);
      }
    }

    // ---- warp-uniform squarings, both streams fused ----
    for (int q = 0; q < s; q++) {
      __syncwarp();                       // prior readers of sA/sB done
      store_row2(sA + li * STR, ca);
      store_row2(sB + li * STR, cb);
      __syncwarp();
      u64 aa[8], ab[8];
#pragma unroll
      for (int p = 0; p < 8; p++) { aa[p] = 0ull; ab[p] = 0ull; }
      mm_pair(sA, sB, ca, cb, aa, ab);
#pragma unroll
      for (int p = 0; p < 8; p++) { ca[p] = aa[p]; cb[p] = ab[p]; }
    }

    // ---- pair product P = M_b @ M_a ----
    __syncwarp();
    store_row2(sA + li * STR, ca);        // M_a -> sA
    __syncwarp();
    u64 P[8];
#pragma unroll
    for (int p = 0; p < 8; p++) P[p] = 0ull;
    mm_row2(sA, cb, P);                   // rows of M_b @ M_a

    // ---- fold: Z = P @ Z ----
    if (kl > 0) {
      u64 acc[8];
#pragma unroll
      for (int p = 0; p < 8; p++) acc[p] = 0ull;
      mm_row2(sZ, P, acc);
#pragma unroll
      for (int p = 0; p < 8; p++) P[p] = acc[p];
    }
    __syncwarp();                         // sZ readers done before overwrite
    store_row2(sZ + li * STR, P);
    __syncwarp();
  }

  // ---- block tree over 8 group products (later factor on the left) ----
  __syncthreads();
  for (int cnt = NGRP; cnt > 1; cnt >>= 1) {
    int pairs = cnt >> 1;
    u64 acc[8];
    bool act = (grp < pairs);
    if (act) {
      u64 lrow[8];
      load_row2(slots + (2 * grp + 1) * GSTR + 2 * SLOT + li * STR, lrow);
#pragma unroll
      for (int p = 0; p < 8; p++) acc[p] = 0ull;
      mm_row2(slots + (2 * grp) * GSTR + 2 * SLOT, lrow, acc);
    }
    __syncthreads();
    if (act) store_row2(slots + grp * GSTR + 2 * SLOT + li * STR, acc);
    __syncthreads();
  }

  const float* Zf = slots + 2 * SLOT;  // group 0's Z slot
  for (int idx = tid; idx < MD * MD; idx += 128) {
    int i = idx >> 4, j = idx & 15;
    g_partial[(b * NCHUNK + chunk) * (MD * MD) + idx] = Zf[i * STR + j];
  }
}

// ---------------------------------------------------------------------------
// Kernel 2: per batch — tree over 32 chunk products, then linear head.
// ---------------------------------------------------------------------------
__global__ void __launch_bounds__(256) dev_finalize(const float* __restrict__ W,
                                                    const float* __restrict__ bias,
                                                    float* __restrict__ out) {
  __shared__ __align__(16) float bufs[NCHUNK * SLOT];  // 40 KB
  const int tid = threadIdx.x;
  const int b   = blockIdx.x;

  for (int idx = tid; idx < NCHUNK * MD * MD; idx += 256) {
    int cm = idx >> 8;
    int r  = idx & 255;
    bufs[cm * SLOT + (r >> 4) * STR + (r & 15)] =
        g_partial[b * NCHUNK * (MD * MD) + idx];
  }
  __syncthreads();

  const int grp = tid >> 4;
  const int li  = tid & 15;
  for (int cnt = NCHUNK; cnt > 1; cnt >>= 1) {
    int pairs = cnt >> 1;
    u64 acc[8];
    if (grp < pairs) {
      u64 lrow[8];
      load_row2(bufs + (2 * grp + 1) * SLOT + li * STR, lrow);
#pragma unroll
      for (int p = 0; p < 8; p++) acc[p] = 0ull;
      mm_row2(bufs + (2 * grp) * SLOT, lrow, acc);
    }
    __syncthreads();
    if (grp < pairs) store_row2(bufs + grp * SLOT + li * STR, acc);
    __syncthreads();
  }

  if (tid < NOUT * 16) {
    const int o = tid >> 4;
    float p = 0.f;
#pragma unroll
    for (int j = 0; j < 16; j++)
      p = fmaf(bufs[li * STR + j], W[o * 256 + li * 16 + j], p);
#pragma unroll
    for (int off = 8; off > 0; off >>= 1)
      p += __shfl_xor_sync(0xffffffffu, p, off);
    if (li == 0) out[b * NOUT + o] = p + bias[o];
  }
}

extern "C" void kernel_launch(void* const* d_in, const int* in_sizes, int n_in,
                              void* d_out, int out_size) {
  const float* X = nullptr; const float* A = nullptr;
  const float* W = nullptr; const float* bv = nullptr;
  for (int i = 0; i < n_in; i++) {
    const float* p = (const float*)d_in[i];
    switch (in_sizes[i]) {
      case BATCH * TLEN * CIN: X = p; break;   // 1048576
      case MD * MD * CIN:      A = p; break;   // 2048
      case NOUT * MD * MD:     W = p; break;   // 2560
      case NOUT:               bv = p; break;  // 10
      default: break;
    }
  }
  float* out = (float*)d_out;

  dim3 g1(NCHUNK, BATCH);
  nopk<<<1, 32>>>();                  // launch-index padding (period 4):
  dev_chunks<<<g1, 128>>>(X, A);      // global launch 5 = dev_chunks -> ncu
  dev_finalize<<<BATCH, 256>>>(W, bv, out);
  nopk<<<1, 32>>>();
}

// round 9
// speedup vs baseline: 1.1572x; 1.1572x over previous
#include <cuda_runtime.h>

typedef unsigned long long u64;

#define BATCH 64
#define TLEN  2048
#define TM1   2047
#define CIN   8
#define MD    16
#define NOUT  10

#define CHUNK  64
#define NCHUNK 32            // 32*64 = 2048 >= 2047 (tail -> identity)
#define NGRP   8             // 16-thread groups per block
#define SPG    8             // steps per group
#define STR    20            // padded row stride (floats)
#define SLOT   (MD*STR)      // 320 floats per matrix slot
#define GSTR   (3*SLOT + 4)  // per-group: sA + sB + sZ + pad

// chunk partial products: [B][NCHUNK][16][16]
__device__ float g_partial[BATCH * NCHUNK * MD * MD];

// ---- packed f32x2 helpers ----
__device__ __forceinline__ float2 unpk(u64 v) {
  float2 r; asm("mov.b64 {%0,%1}, %2;" : "=f"(r.x), "=f"(r.y) : "l"(v)); return r;
}
__device__ __forceinline__ u64 pk2(float x, float y) {
  u64 r; asm("mov.b64 %0, {%1,%2};" : "=l"(r) : "f"(x), "f"(y)); return r;
}
__device__ __forceinline__ u64 bc2(float x) {
  u64 r; asm("mov.b64 %0, {%1,%1};" : "=l"(r) : "f"(x)); return r;
}
__device__ __forceinline__ void fma2(u64& d, u64 a, u64 b) {
  asm("fma.rn.f32x2 %0, %1, %2, %0;" : "+l"(d) : "l"(a), "l"(b));
}
__device__ __forceinline__ u64 fma2v(u64 a, u64 b, u64 c) {
  u64 d; asm("fma.rn.f32x2 %0, %1, %2, %3;" : "=l"(d) : "l"(a), "l"(b), "l"(c)); return d;
}
__device__ __forceinline__ u64 mul2(u64 a, u64 b) {
  u64 d; asm("mul.rn.f32x2 %0, %1, %2;" : "=l"(d) : "l"(a), "l"(b)); return d;
}

// acc += av * Brow (16 floats in smem, 16B-aligned)
__device__ __forceinline__ void row_fma(u64* acc, u64 av, const float* brow) {
  const ulonglong2* bp = reinterpret_cast<const ulonglong2*>(brow);
  ulonglong2 b0 = bp[0], b1 = bp[1], b2 = bp[2], b3 = bp[3];
  fma2(acc[0], av, b0.x); fma2(acc[1], av, b0.y);
  fma2(acc[2], av, b1.x); fma2(acc[3], av, b1.y);
  fma2(acc[4], av, b2.x); fma2(acc[5], av, b2.y);
  fma2(acc[6], av, b3.x); fma2(acc[7], av, b3.y);
}

// acc(row) += a(row, packed regs) @ Bm (16x16 in smem, row stride STR)
__device__ __forceinline__ void mm_row2(const float* __restrict__ Bm,
                                        const u64* __restrict__ a,
                                        u64* __restrict__ acc) {
#pragma unroll
  for (int kp = 0; kp < 8; kp++) {
    float2 ak = unpk(a[kp]);
    row_fma(acc, bc2(ak.x), Bm + (2 * kp) * STR);
    row_fma(acc, bc2(ak.y), Bm + (2 * kp + 1) * STR);
  }
}

__device__ __forceinline__ void store_row2(float* dst, const u64* v) {
  ulonglong2* dp = reinterpret_cast<ulonglong2*>(dst);
  dp[0] = make_ulonglong2(v[0], v[1]);
  dp[1] = make_ulonglong2(v[2], v[3]);
  dp[2] = make_ulonglong2(v[4], v[5]);
  dp[3] = make_ulonglong2(v[6], v[7]);
}
__device__ __forceinline__ void load_row2(const float* src, u64* v) {
  const ulonglong2* sp = reinterpret_cast<const ulonglong2*>(src);
  ulonglong2 a = sp[0], b = sp[1], c = sp[2], d = sp[3];
  v[0] = a.x; v[1] = a.y; v[2] = b.x; v[3] = b.y;
  v[4] = c.x; v[5] = c.y; v[6] = d.x; v[7] = d.y;
}

// pad kernel (period-3 launch pattern c,f,n -> ncu "-s 5" lands on dev_chunks)
__global__ void nopk() {}

// ---------------------------------------------------------------------------
// Kernel 1: per (batch, chunk of 64 steps). R6 core: 16-thread groups,
// 1 row/thread, commuting-Horner Taylor-6 at theta<=0.25, warp-uniform
// squarings. NEW: ping-pong squaring buffers -> 1 sync per squaring,
// 0 syncs in Horner.
// ---------------------------------------------------------------------------
__global__ void __launch_bounds__(128) dev_chunks(const float* __restrict__ X,
                                                  const float* __restrict__ A) {
  __shared__ __align__(16) float Gs[CIN * SLOT];
  __shared__ __align__(16) float slots[NGRP * GSTR];
  __shared__ float dxs[CHUNK * CIN];

  const int tid   = threadIdx.x;
  const int chunk = blockIdx.x;
  const int b     = blockIdx.y;
  const int base  = chunk * CHUNK;

  for (int idx = tid; idx < CIN * MD * MD; idx += 128) {
    int c = idx >> 8;
    int i = (idx >> 4) & 15;
    int j = idx & 15;
    Gs[c * SLOT + i * STR + j] =
        A[(i * MD + j) * CIN + c] - A[(j * MD + i) * CIN + c];
  }
  for (int idx = tid; idx < CHUNK * CIN; idx += 128) {
    int k = idx >> 3;
    int c = idx & 7;
    int t = base + k;
    float v = 0.f;
    if (t < TM1)
      v = X[(b * TLEN + t + 1) * CIN + c] - X[(b * TLEN + t) * CIN + c];
    dxs[idx] = v;
  }
  __syncthreads();

  const int grp = tid >> 4;
  const int li  = tid & 15;
  float* sA = slots + grp * GSTR;   // S + odd squarings
  float* sB = sA + SLOT;            // even squarings
  float* sZ = sB + SLOT;            // running product Z

  u64 idp[8];
#pragma unroll
  for (int p = 0; p < 8; p++)
    idp[p] = pk2((li == 2 * p) ? 1.f : 0.f, (li == 2 * p + 1) ? 1.f : 0.f);

  u64 cur[8];

  for (int kl = 0; kl < SPG; kl++) {
    const int kk = grp * SPG + kl;

    // ---- S row (packed) ----
    u64 S[8];
#pragma unroll
    for (int p = 0; p < 8; p++) S[p] = 0ull;
#pragma unroll
    for (int c = 0; c < CIN; c++) {
      u64 d2 = bc2(dxs[kk * CIN + c]);
      row_fma(S, d2, Gs + c * SLOT + li * STR);
    }

    // ---- norm: min(inf, Frobenius/sqrt(2)); warp-uniform s ----
    float rs = 0.f, fr = 0.f;
#pragma unroll
    for (int p = 0; p < 8; p++) {
      float2 t = unpk(S[p]);
      rs += fabsf(t.x) + fabsf(t.y);
      fr = fmaf(t.x, t.x, fr);
      fr = fmaf(t.y, t.y, fr);
    }
#pragma unroll
    for (int off = 1; off < 16; off <<= 1) {
      rs = fmaxf(rs, __shfl_xor_sync(0xffffffffu, rs, off));
      fr += __shfl_xor_sync(0xffffffffu, fr, off);
    }
    float nrm = fminf(rs, sqrtf(0.5f * fr));
    nrm = fmaxf(nrm, __shfl_xor_sync(0xffffffffu, nrm, 16));  // warp-uniform
    int s = 0;
    if (nrm > 0.f) {
      int e;
      frexpf(nrm, &e);   // nrm = f * 2^e, f in [0.5,1)
      s = e + 2;         // ||S/2^s|| <= 0.25
      if (s < 0) s = 0;
      if (s > 40) s = 40;
    }
    const u64 sc2 = bc2(__int_as_float((127 - s) << 23));  // exact 2^-s
#pragma unroll
    for (int p = 0; p < 8; p++) S[p] = mul2(S[p], sc2);

    // ---- store S once (trailing syncs of previous step cover old readers)
    store_row2(sA + li * STR, S);
    // init Horner from registers while the STS is in flight
    {
      const u64 c6 = bc2(1.f / 6.f);
#pragma unroll
      for (int p = 0; p < 8; p++) cur[p] = fma2v(S[p], c6, idp[p]);
    }
    __syncwarp();

    // ---- commuting-Horner Taylor-6: no syncs, S read from sA ----
#pragma unroll
    for (int k = 5; k >= 1; k--) {
      u64 acc[8];
#pragma unroll
      for (int p = 0; p < 8; p++) acc[p] = 0ull;
      mm_row2(sA, cur, acc);                  // acc = cur @ S (== S @ cur)
      const u64 inv = bc2(1.f / (float)k);
#pragma unroll
      for (int p = 0; p < 8; p++) cur[p] = fma2v(acc[p], inv, idp[p]);
    }

    // ---- warp-uniform squarings: ping-pong buffers, 1 sync each ----
    // q even -> sB (last read two mms ago or never this step), q odd -> sA.
    for (int q = 0; q < s; q++) {
      float* buf = (q & 1) ? sA : sB;
      store_row2(buf + li * STR, cur);
      __syncwarp();                           // store visible + old readers done
      u64 acc[8];
#pragma unroll
      for (int p = 0; p < 8; p++) acc[p] = 0ull;
      mm_row2(buf, cur, acc);
#pragma unroll
      for (int p = 0; p < 8; p++) cur[p] = acc[p];
    }

    // ---- fold: Z = M @ Z ----
    if (kl > 0) {
      u64 acc[8];
#pragma unroll
      for (int p = 0; p < 8; p++) acc[p] = 0ull;
      mm_row2(sZ, cur, acc);
#pragma unroll
      for (int p = 0; p < 8; p++) cur[p] = acc[p];
    }
    __syncwarp();                             // sZ readers done before overwrite
    store_row2(sZ + li * STR, cur);
    __syncwarp();
  }

  // ---- block tree over 8 group products (later factor on the left) ----
  __syncthreads();
  for (int cnt = NGRP; cnt > 1; cnt >>= 1) {
    int pairs = cnt >> 1;
    u64 acc[8];
    bool act = (grp < pairs);
    if (act) {
      u64 lrow[8];
      load_row2(slots + (2 * grp + 1) * GSTR + 2 * SLOT + li * STR, lrow);
#pragma unroll
      for (int p = 0; p < 8; p++) acc[p] = 0ull;
      mm_row2(slots + (2 * grp) * GSTR + 2 * SLOT, lrow, acc);
    }
    __syncthreads();
    if (act) store_row2(slots + grp * GSTR + 2 * SLOT + li * STR, acc);
    __syncthreads();
  }

  const float* Zf = slots + 2 * SLOT;  // group 0's Z slot
  for (int idx = tid; idx < MD * MD; idx += 128) {
    int i = idx >> 4, j = idx & 15;
    g_partial[(b * NCHUNK + chunk) * (MD * MD) + idx] = Zf[i * STR + j];
  }
}

// ---------------------------------------------------------------------------
// Kernel 2: per batch — tree over 32 chunk products, then linear head.
// ---------------------------------------------------------------------------
__global__ void __launch_bounds__(256) dev_finalize(const float* __restrict__ W,
                                                    const float* __restrict__ bias,
                                                    float* __restrict__ out) {
  __shared__ __align__(16) float bufs[NCHUNK * SLOT];  // 40 KB
  const int tid = threadIdx.x;
  const int b   = blockIdx.x;

  for (int idx = tid; idx < NCHUNK * MD * MD; idx += 256) {
    int cm = idx >> 8;
    int r  = idx & 255;
    bufs[cm * SLOT + (r >> 4) * STR + (r & 15)] =
        g_partial[b * NCHUNK * (MD * MD) + idx];
  }
  __syncthreads();

  const int grp = tid >> 4;
  const int li  = tid & 15;
  for (int cnt = NCHUNK; cnt > 1; cnt >>= 1) {
    int pairs = cnt >> 1;
    u64 acc[8];
    if (grp < pairs) {
      u64 lrow[8];
      load_row2(bufs + (2 * grp + 1) * SLOT + li * STR, lrow);
#pragma unroll
      for (int p = 0; p < 8; p++) acc[p] = 0ull;
      mm_row2(bufs + (2 * grp) * SLOT, lrow, acc);
    }
    __syncthreads();
    if (grp < pairs) store_row2(bufs + grp * SLOT + li * STR, acc);
    __syncthreads();
  }

  if (tid < NOUT * 16) {
    const int o = tid >> 4;
    float p = 0.f;
#pragma unroll
    for (int j = 0; j < 16; j++)
      p = fmaf(bufs[li * STR + j], W[o * 256 + li * 16 + j], p);
#pragma unroll
    for (int off = 8; off > 0; off >>= 1)
      p += __shfl_xor_sync(0xffffffffu, p, off);
    if (li == 0) out[b * NOUT + o] = p + bias[o];
  }
}

extern "C" void kernel_launch(void* const* d_in, const int* in_sizes, int n_in,
                              void* d_out, int out_size) {
  const float* X = nullptr; const float* A = nullptr;
  const float* W = nullptr; const float* bv = nullptr;
  for (int i = 0; i < n_in; i++) {
    const float* p = (const float*)d_in[i];
    switch (in_sizes[i]) {
      case BATCH * TLEN * CIN: X = p; break;   // 1048576
      case MD * MD * CIN:      A = p; break;   // 2048
      case NOUT * MD * MD:     W = p; break;   // 2560
      case NOUT:               bv = p; break;  // 10
      default: break;
    }
  }
  float* out = (float*)d_out;

  dim3 g1(NCHUNK, BATCH);
  dev_chunks<<<g1, 128>>>(X, A);      // period-3 pattern: c,f,n
  dev_finalize<<<BATCH, 256>>>(W, bv, out);
  nopk<<<1, 32>>>();                  // ncu -s 5 -> global idx 5 = dev_chunks
}